// round 17
// baseline (speedup 1.0000x reference)
#include <cuda_runtime.h>
#include <cuda_fp16.h>
#include <math.h>
#include <cstdint>
#include <mma.h>

using namespace nvcuda;

#define BSZ     4
#define LSEQ    4096
#define DMODEL  768
#define DSTATE  128
#define HEADDIM 64
#define DINNER  1536
#define NHEADS  24
#define DPROJ   3352       // logical in-proj width
#define DPROJP  3456       // padded to 27*128
#define CONVCH  1792       // 1536 + 2*128
#define EPSV    1e-5f
#define NBT     (BSZ*LSEQ) // 16384

#define QCH     128                 // scan chunk length
#define NCH     (LSEQ/QCH)          // 32 chunks
#define NBH     (BSZ*NHEADS)        // 96
#define STATE_SZ (HEADDIM*DSTATE)   // 8192 per (b,h)

#define WINSZ   (DMODEL*DPROJP)     // 2,654,208
#define WOUTSZ  (DINNER*DMODEL)     // 1,179,648
#define CVTB    ((WINSZ + WOUTSZ) / 1024)   // 3744 (exact)

// scanAg smem geometry
#define BWLD    136                 // half stride of (w*B) tile row
#define XLD     72                  // half stride of X tile row
#define SCANA_SMEM (128*BWLD*2 + 128*XLD*2 + 128*4)   // 53,760 B

// scanC-SSD smem geometry
#define CLD     136                 // half stride, n/s dim tiles (C, B/M)
#define PLD     72                  // half stride, p dim tiles (X, H0); also fp32 y ld
#define SLD     132                 // fp32 stride of S
#define SSD_SMEM ((2*128*CLD + 2*128*PLD)*2 + (128*SLD + 256)*4)  // 175,104 B

typedef unsigned long long u64;

// ---------------- scratch (static device globals) ---------------------------
__device__ __half g_uh   [(size_t)NBT * DMODEL];    // LN output, fp16
__device__ float  g_zx   [(size_t)NBT * DPROJP];    // GEMM1 out, fp32
__device__ float  g_xbc  [(size_t)NBT * CONVCH];
__device__ float  g_y    [(size_t)NBT * DINNER];    // scan out, fp32
__device__ __half g_yh   [(size_t)NBT * DINNER];    // gated+normed, fp16
__device__ float  g_dA   [NBT * NHEADS];
__device__ float  g_dt   [NBT * NHEADS];
__device__ __half g_winh [(size_t)WINSZ];           // fp16, padded cols
__device__ __half g_wouth[(size_t)WOUTSZ];          // fp16
// chunked-scan scratch: layout [bh*NCH + c][n(128)][p(64)]
__device__ float  g_U    [(size_t)NBH * NCH * STATE_SZ];   // chunk local sums
__device__ float  g_hc   [(size_t)NBH * NCH * STATE_SZ];   // chunk start states
__device__ float  g_P    [NBH * NCH];                      // chunk decay products

// ---------------- helpers ----------------------------------------------------
__device__ __forceinline__ unsigned smem_u32(const void* p) {
    return (unsigned)__cvta_generic_to_shared(p);
}
#define CP16(dst, src)  asm volatile("cp.async.cg.shared.global [%0], [%1], 16;" :: "r"(dst), "l"(src))
#define CP_COMMIT()     asm volatile("cp.async.commit_group;")
#define CP_WAIT(n)      asm volatile("cp.async.wait_group %0;" :: "n"(n))

__device__ __forceinline__ float block_reduce_sum(float v, float* red) {
    #pragma unroll
    for (int o = 16; o; o >>= 1) v += __shfl_down_sync(0xffffffffu, v, o);
    int lane = threadIdx.x & 31, wid = threadIdx.x >> 5;
    if (lane == 0) red[wid] = v;
    __syncthreads();
    int nw = blockDim.x >> 5;
    v = (threadIdx.x < nw) ? red[threadIdx.x] : 0.f;
    if (wid == 0) {
        #pragma unroll
        for (int o = 16; o; o >>= 1) v += __shfl_down_sync(0xffffffffu, v, o);
        if (lane == 0) red[0] = v;
    }
    __syncthreads();
    return red[0];
}

// ---------------- 0+1) LayerNorm (fp16 out) + weight cvt (grid tail) ---------
__global__ void __launch_bounds__(256) lnfused_kernel(const float* __restrict__ x,
                                                      const float* __restrict__ w,
                                                      const float* __restrict__ b,
                                                      const float* __restrict__ Wi,
                                                      const float* __restrict__ Wo) {
    if (blockIdx.x < NBT) {
        __shared__ float red[32];
        int row = blockIdx.x;
        const float* xr = x + (size_t)row * DMODEL;
        float v[3], s = 0.f, ss = 0.f;
        #pragma unroll
        for (int i = 0; i < 3; i++) {
            v[i] = xr[threadIdx.x + i * 256];
            s += v[i]; ss += v[i] * v[i];
        }
        float tot = block_reduce_sum(s, red);
        __syncthreads();
        float tot2 = block_reduce_sum(ss, red);
        float mu  = tot / DMODEL;
        float var = tot2 / DMODEL - mu * mu;
        float inv = rsqrtf(var + EPSV);
        __half* ur = g_uh + (size_t)row * DMODEL;
        #pragma unroll
        for (int i = 0; i < 3; i++) {
            int c = threadIdx.x + i * 256;
            ur[c] = __float2half_rn((v[i] - mu) * inv * w[c] + b[c]);
        }
    } else {
        int e0 = (blockIdx.x - NBT) * 1024 + threadIdx.x * 4;
        #pragma unroll
        for (int j = 0; j < 4; j++) {
            int e = e0 + j;
            if (e < WINSZ) {
                int r = e / DPROJP, c = e - r * DPROJP;
                g_winh[e] = (c < DPROJ)
                          ? __float2half_rn(Wi[(size_t)r * DPROJ + c])
                          : __half(0.f);
            } else {
                int i2 = e - WINSZ;
                g_wouth[i2] = __float2half_rn(Wo[i2]);
            }
        }
    }
}

// ---------------- FP16 wmma GEMM, 3-stage cp.async ring ----------------------
#define GSTG 3
#define ASTRH 40
#define BSTRH 136
#define A_ELEMH (128 * ASTRH)
#define B_ELEMH (32 * BSTRH)
#define STG_ELEMH (A_ELEMH + B_ELEMH)
#define GEMM_SMEM (GSTG * STG_ELEMH * 2)   // 56,832 B

template<bool RESID>
__global__ void __launch_bounds__(256, 2)
gemm_fp16(const __half* __restrict__ A, const __half* __restrict__ B,
          float* __restrict__ C, const float* __restrict__ R,
          int NP, int NB, int K) {
    extern __shared__ __half hsm[];
    __half* As = hsm;
    __half* Bs = hsm + GSTG * A_ELEMH;

    int tid  = threadIdx.x;
    int warp = tid >> 5, wm = warp >> 1, wn = warp & 1;
    int row0 = blockIdx.y * 128, col0 = blockIdx.x * 128;

    wmma::fragment<wmma::accumulator, 16, 16, 16, float> acc[2][4];
    #pragma unroll
    for (int i = 0; i < 2; i++)
        #pragma unroll
        for (int j = 0; j < 4; j++) wmma::fill_fragment(acc[i][j], 0.f);

    int a_r = tid >> 2, a_c = (tid & 3) * 8;
    int b_r = tid >> 4, b_c = (tid & 15) * 8;

    auto issue_stage = [&](int s, int k0) {
        __half* Ad = As + s * A_ELEMH;
        __half* Bd = Bs + s * B_ELEMH;
        #pragma unroll
        for (int u = 0; u < 2; u++) {
            int r = a_r + u * 64;
            CP16(smem_u32(Ad + r * ASTRH + a_c),
                 A + (size_t)(row0 + r) * K + k0 + a_c);
        }
        #pragma unroll
        for (int u = 0; u < 2; u++) {
            int r = b_r + u * 16;
            CP16(smem_u32(Bd + r * BSTRH + b_c),
                 B + (size_t)(k0 + r) * NB + col0 + b_c);
        }
    };

    int nk = K / 32;
    issue_stage(0, 0);  CP_COMMIT();
    issue_stage(1, 32); CP_COMMIT();

    for (int i = 0; i < nk; i++) {
        CP_WAIT(1);
        __syncthreads();
        if (i + 2 < nk) issue_stage((i + 2) % GSTG, (i + 2) * 32);
        CP_COMMIT();

        int s = i % GSTG;
        const __half* Ap = As + s * A_ELEMH;
        const __half* Bp = Bs + s * B_ELEMH;
        #pragma unroll
        for (int kk = 0; kk < 32; kk += 16) {
            wmma::fragment<wmma::matrix_a, 16, 16, 16, __half, wmma::row_major> af[2];
            #pragma unroll
            for (int a = 0; a < 2; a++)
                wmma::load_matrix_sync(af[a], Ap + (wm * 32 + a * 16) * ASTRH + kk, ASTRH);
            #pragma unroll
            for (int b2 = 0; b2 < 4; b2++) {
                wmma::fragment<wmma::matrix_b, 16, 16, 16, __half, wmma::row_major> bf;
                wmma::load_matrix_sync(bf, Bp + kk * BSTRH + wn * 64 + b2 * 16, BSTRH);
                wmma::mma_sync(acc[0][b2], af[0], bf, acc[0][b2]);
                wmma::mma_sync(acc[1][b2], af[1], bf, acc[1][b2]);
            }
        }
    }

    #pragma unroll
    for (int i = 0; i < 2; i++)
        #pragma unroll
        for (int j = 0; j < 4; j++) {
            int r = row0 + wm * 32 + i * 16;
            int c = col0 + wn * 64 + j * 16;
            float* Cp = C + (size_t)r * NP + c;
            if (RESID) {
                wmma::fragment<wmma::accumulator, 16, 16, 16, float> rf;
                wmma::load_matrix_sync(rf, R + (size_t)r * NP + c, NP, wmma::mem_row_major);
                #pragma unroll
                for (int e = 0; e < rf.num_elements; e++) acc[i][j].x[e] += rf.x[e];
            }
            wmma::store_matrix_sync(Cp, acc[i][j], NP, wmma::mem_row_major);
        }
}

// ---------------- 2) conv(K=4)+SiLU with dt/dA in grid tail -------------------
#define CONVBLK ((NBT * CONVCH) / 256)
#define DTBLK   ((NBT * NHEADS) / 256)
__global__ void __launch_bounds__(256) convdt_kernel(const float* __restrict__ cw,
                                                     const float* __restrict__ cb,
                                                     const float* __restrict__ dt_bias,
                                                     const float* __restrict__ A_log) {
    if (blockIdx.x < CONVBLK) {
        int id = blockIdx.x * 256 + threadIdx.x;
        int c  = id % CONVCH;
        int bt = id / CONVCH;
        int t  = bt % LSEQ;
        int b  = bt / LSEQ;
        const float* src = g_zx + (size_t)(b * LSEQ) * DPROJP + DINNER + c;
        float acc = cb[c];
        #pragma unroll
        for (int k = 0; k < 4; k++) {
            int ti = t - 3 + k;
            if (ti >= 0) acc = fmaf(cw[c * 4 + k], src[(size_t)ti * DPROJP], acc);
        }
        g_xbc[id] = acc / (1.f + expf(-acc));   // SiLU
    } else {
        int id = (blockIdx.x - CONVBLK) * 256 + threadIdx.x;
        int h  = id % NHEADS;
        int bt = id / NHEADS;
        float v  = g_zx[(size_t)bt * DPROJP + (DINNER + DINNER + 2 * DSTATE) + h] + dt_bias[h];
        float sp = (v > 20.f) ? v : log1pf(expf(v));
        g_dt[id] = sp;
        g_dA[id] = expf(-expf(A_log[h]) * sp);
    }
}

// ---------------- 3a) scan pass A as tensor-core GEMM -------------------------
// U[n][p] = sum_s w_s * B_s[n] * x_s[p], w_s = dt_s * prod_{u>s} dA_u.
__global__ void __launch_bounds__(256) scanAg_kernel() {
    extern __shared__ char dyn[];
    __half* sBw = (__half*)dyn;                         // [128][BWLD]
    __half* sXh = sBw + 128 * BWLD;                     // [128][XLD]
    float*  sW  = (float*)(sXh + 128 * XLD);            // [128]

    int blk = blockIdx.x;
    int c  = blk & (NCH - 1);
    int bh = blk >> 5;
    int b = bh / NHEADS, h = bh % NHEADS;
    int tid = threadIdx.x;
    int wid = tid >> 5, lane = tid & 31;
    int t0 = c * QCH;

    const float* base = g_xbc + (size_t)(b * LSEQ + t0) * CONVCH;
    const float* dAb  = g_dA + (b * LSEQ + t0) * NHEADS + h;
    const float* dtb  = g_dt + (b * LSEQ + t0) * NHEADS + h;

    // warp 0: suffix decay products + weights + P
    if (wid == 0) {
        float seg[4];
        float q = 1.f;
        #pragma unroll
        for (int k = 0; k < 4; k++) {
            seg[k] = dAb[(lane * 4 + k) * NHEADS];
            q *= seg[k];
        }
        float pr = q;   // will become prod over lanes >= lane
        #pragma unroll
        for (int o = 1; o < 32; o <<= 1) {
            float v = __shfl_down_sync(0xffffffffu, pr, o);
            if (lane + o < 32) pr *= v;
        }
        float Sl = __shfl_down_sync(0xffffffffu, pr, 1);   // prod over lanes > lane
        if (lane == 31) Sl = 1.f;
        float Ptot = __shfl_sync(0xffffffffu, pr, 0);
        if (lane == 0) g_P[blk] = Ptot;
        float run = Sl;                                    // prod dA_u, u > s
        #pragma unroll
        for (int k = 3; k >= 0; k--) {
            int s = lane * 4 + k;
            sW[s] = dtb[s * NHEADS] * run;
            run *= seg[k];
        }
    }
    __syncthreads();

    // stage (w*B) and x as fp16
    {
        int s0 = tid >> 1;
        int nh = (tid & 1) * 64;
        float wv = sW[s0];
        const float* Brow = base + (size_t)s0 * CONVCH + DINNER + nh;
        __half* dst = sBw + s0 * BWLD + nh;
        #pragma unroll
        for (int j = 0; j < 16; j++) {
            float4 v = *(const float4*)(Brow + j * 4);
            *(__half2*)(dst + j * 4)     = __floats2half2_rn(v.x * wv, v.y * wv);
            *(__half2*)(dst + j * 4 + 2) = __floats2half2_rn(v.z * wv, v.w * wv);
        }
        int p0 = (tid & 1) * 32;
        const float* Xrow = base + (size_t)s0 * CONVCH + h * HEADDIM + p0;
        __half* xdst = sXh + s0 * XLD + p0;
        #pragma unroll
        for (int j = 0; j < 8; j++) {
            float4 v = *(const float4*)(Xrow + j * 4);
            *(__half2*)(xdst + j * 4)     = __floats2half2_rn(v.x, v.y);
            *(__half2*)(xdst + j * 4 + 2) = __floats2half2_rn(v.z, v.w);
        }
    }
    __syncthreads();

    // wmma: U = (wB)^T @ X  (m=128 n-dim, n=64 p-dim, k=128 steps)
    int wm = wid >> 1, wn = wid & 1;
    wmma::fragment<wmma::accumulator, 16, 16, 16, float> acc[2][2];
    #pragma unroll
    for (int i = 0; i < 2; i++)
        #pragma unroll
        for (int j = 0; j < 2; j++) wmma::fill_fragment(acc[i][j], 0.f);

    #pragma unroll
    for (int kk = 0; kk < QCH; kk += 16) {
        wmma::fragment<wmma::matrix_a, 16, 16, 16, __half, wmma::col_major> af[2];
        wmma::fragment<wmma::matrix_b, 16, 16, 16, __half, wmma::row_major> bf[2];
        #pragma unroll
        for (int i = 0; i < 2; i++)
            wmma::load_matrix_sync(af[i], sBw + kk * BWLD + wm * 32 + i * 16, BWLD);
        #pragma unroll
        for (int j = 0; j < 2; j++)
            wmma::load_matrix_sync(bf[j], sXh + kk * XLD + wn * 32 + j * 16, XLD);
        #pragma unroll
        for (int i = 0; i < 2; i++)
            #pragma unroll
            for (int j = 0; j < 2; j++)
                wmma::mma_sync(acc[i][j], af[i], bf[j], acc[i][j]);
    }

    float* Up = g_U + (size_t)blk * STATE_SZ;           // [n][p], ld = 64
    #pragma unroll
    for (int i = 0; i < 2; i++)
        #pragma unroll
        for (int j = 0; j < 2; j++)
            wmma::store_matrix_sync(Up + (wm * 32 + i * 16) * HEADDIM + wn * 32 + j * 16,
                                    acc[i][j], HEADDIM, wmma::mem_row_major);
}

// ---------------- 3b) scan pass B: sequential chunk-state chain --------------
__global__ void __launch_bounds__(256) scanB_kernel() {
    int bh = blockIdx.x >> 3, part = blockIdx.x & 7;
    int e0 = part * 1024 + threadIdx.x;
    float hcur[4] = {0.f, 0.f, 0.f, 0.f};
    for (int c = 0; c < NCH; c++) {
        size_t off = (size_t)(bh * NCH + c) * STATE_SZ + e0;
        float P = g_P[bh * NCH + c];
        #pragma unroll
        for (int k = 0; k < 4; k++) {
            g_hc[off + k * 256] = hcur[k];
            hcur[k] = fmaf(P, hcur[k], g_U[off + k * 256]);
        }
    }
}

// ---------------- 3c) scan pass C: SSD form (all tensor-core) ----------------
// y_t = exp(sig_t)*(C_t . h0) + sum_{s<=t} exp(sig_t - sig_s)*dt_s*(C_t.B_s)*x_s
//       + Dh * x_t,   sig_t = -exp(A_log_h) * sum_{u<=t} dt_u  (exact ln dA).
// Per block: S = C*B^T (wmma) -> mask/exp -> y = Csig*H0 + M*X (wmma).
__global__ void __launch_bounds__(256) scanC_ssd(const float* __restrict__ Dv,
                                                 const float* __restrict__ A_log) {
    extern __shared__ char dyn[];
    __half* sC  = (__half*)dyn;                 // [128][CLD]  t x n
    __half* sB  = sC + 128 * CLD;               // [128][CLD]  s x n; later M (t x s)
    __half* sX  = sB + 128 * CLD;               // [128][PLD]  s x p
    __half* sH0 = sX + 128 * PLD;               // [128][PLD]  n x p
    float*  sS  = (float*)(sH0 + 128 * PLD);    // [128][SLD]  t x s; later y (t x p, ld PLD)
    float*  sSig = sS + 128 * SLD;              // [128]
    float*  sDt  = sSig + 128;                  // [128]

    int blk = blockIdx.x;
    int c  = blk & (NCH - 1);
    int bh = blk >> 5;
    int b = bh / NHEADS, h = bh % NHEADS;
    int tid = threadIdx.x;
    int wid = tid >> 5, lane = tid & 31;
    int t0 = c * QCH;

    const float* base = g_xbc + (size_t)(b * LSEQ + t0) * CONVCH;
    const float* dtb  = g_dt + (b * LSEQ + t0) * NHEADS + h;
    const float* Hp   = g_hc + (size_t)blk * STATE_SZ;
    float Dh = Dv[h];
    float* ybase = g_y + (size_t)(b * LSEQ + t0) * DINNER + h * HEADDIM;

    if (tid < QCH) sDt[tid] = dtb[tid * NHEADS];

    // stage C, B (fp16, 2 thr/row) and X, H0 (fp16, 2 thr/row, 32 p each)
    {
        int r  = tid >> 1;
        int nh = (tid & 1) * 64;
        const float* Crow = base + (size_t)r * CONVCH + DINNER + DSTATE + nh;
        const float* Brow = base + (size_t)r * CONVCH + DINNER + nh;
        __half* cdst = sC + r * CLD + nh;
        __half* bdst = sB + r * CLD + nh;
        #pragma unroll
        for (int j = 0; j < 16; j++) {
            float4 v = *(const float4*)(Crow + j * 4);
            *(__half2*)(cdst + j * 4)     = __floats2half2_rn(v.x, v.y);
            *(__half2*)(cdst + j * 4 + 2) = __floats2half2_rn(v.z, v.w);
            float4 u = *(const float4*)(Brow + j * 4);
            *(__half2*)(bdst + j * 4)     = __floats2half2_rn(u.x, u.y);
            *(__half2*)(bdst + j * 4 + 2) = __floats2half2_rn(u.z, u.w);
        }
        int p0 = (tid & 1) * 32;
        const float* Xrow = base + (size_t)r * CONVCH + h * HEADDIM + p0;
        const float* Hrow = Hp + (size_t)r * HEADDIM + p0;
        __half* xdst = sX  + r * PLD + p0;
        __half* hdst = sH0 + r * PLD + p0;
        #pragma unroll
        for (int j = 0; j < 8; j++) {
            float4 v = *(const float4*)(Xrow + j * 4);
            *(__half2*)(xdst + j * 4)     = __floats2half2_rn(v.x, v.y);
            *(__half2*)(xdst + j * 4 + 2) = __floats2half2_rn(v.z, v.w);
            float4 u = *(const float4*)(Hrow + j * 4);
            *(__half2*)(hdst + j * 4)     = __floats2half2_rn(u.x, u.y);
            *(__half2*)(hdst + j * 4 + 2) = __floats2half2_rn(u.z, u.w);
        }
    }
    __syncthreads();

    // warp 0: inclusive prefix sums -> sig_t = -aexp * cumsum(dt)
    if (wid == 0) {
        float aexp = __expf(A_log[h]);
        float d0 = sDt[lane * 4 + 0], d1 = sDt[lane * 4 + 1];
        float d2 = sDt[lane * 4 + 2], d3 = sDt[lane * 4 + 3];
        float run = d0 + d1 + d2 + d3;
        float sc = run;
        #pragma unroll
        for (int o = 1; o < 32; o <<= 1) {
            float v = __shfl_up_sync(0xffffffffu, sc, o);
            if (lane >= o) sc += v;
        }
        float base0 = sc - run;
        float c0 = base0 + d0, c1 = c0 + d1, c2 = c1 + d2, c3 = c2 + d3;
        sSig[lane * 4 + 0] = -aexp * c0;
        sSig[lane * 4 + 1] = -aexp * c1;
        sSig[lane * 4 + 2] = -aexp * c2;
        sSig[lane * 4 + 3] = -aexp * c3;
    }

    // GEMM-S: S[t][s] = sum_n C_t[n] B_s[n]; warp tile 32(t) x 64(s)
    {
        int wm = wid >> 1, wn = wid & 1;
        wmma::fragment<wmma::accumulator, 16, 16, 16, float> acc[2][4];
        #pragma unroll
        for (int i = 0; i < 2; i++)
            #pragma unroll
            for (int j = 0; j < 4; j++) wmma::fill_fragment(acc[i][j], 0.f);
        #pragma unroll
        for (int kk = 0; kk < 128; kk += 16) {
            wmma::fragment<wmma::matrix_a, 16, 16, 16, __half, wmma::row_major> af[2];
            wmma::fragment<wmma::matrix_b, 16, 16, 16, __half, wmma::col_major> bf[4];
            #pragma unroll
            for (int i = 0; i < 2; i++)
                wmma::load_matrix_sync(af[i], sC + (wm * 32 + i * 16) * CLD + kk, CLD);
            #pragma unroll
            for (int j = 0; j < 4; j++)
                wmma::load_matrix_sync(bf[j], sB + (wn * 64 + j * 16) * CLD + kk, CLD);
            #pragma unroll
            for (int i = 0; i < 2; i++)
                #pragma unroll
                for (int j = 0; j < 4; j++)
                    wmma::mma_sync(acc[i][j], af[i], bf[j], acc[i][j]);
        }
        #pragma unroll
        for (int i = 0; i < 2; i++)
            #pragma unroll
            for (int j = 0; j < 4; j++)
                wmma::store_matrix_sync(sS + (wm * 32 + i * 16) * SLD + wn * 64 + j * 16,
                                        acc[i][j], SLD, wmma::mem_row_major);
    }
    __syncthreads();

    // mask phase: M[t][s] = (s<=t) ? S*exp(sig_t-sig_s)*dt_s : 0  (into sB);
    // scale C rows by exp(sig_t) in place (Csig).
    {
        int t  = tid >> 1;
        int s0 = (tid & 1) * 64;
        float sig_t = sSig[t];
        __half* Mrow = sB + t * CLD + s0;
        const float* Srow = sS + t * SLD + s0;
        #pragma unroll 8
        for (int j = 0; j < 32; j++) {
            int s = s0 + j * 2;
            float m0 = (s     <= t) ? Srow[j*2]   * __expf(sig_t - sSig[s])   * sDt[s]   : 0.f;
            float m1 = (s + 1 <= t) ? Srow[j*2+1] * __expf(sig_t - sSig[s+1]) * sDt[s+1] : 0.f;
            *(__half2*)(Mrow + j * 2) = __floats2half2_rn(m0, m1);
        }
        float at = __expf(sig_t);
        __half2 at2 = __floats2half2_rn(at, at);
        __half2* Crow = (__half2*)(sC + t * CLD + s0);
        #pragma unroll 8
        for (int j = 0; j < 32; j++) Crow[j] = __hmul2(Crow[j], at2);
    }
    __syncthreads();

    // GEMM-Y: y = Csig @ H0 (k=n) + M @ X (k=s); warp tile 32(t) x 32(p)
    {
        int wm = wid >> 1, wn = wid & 1;
        wmma::fragment<wmma::accumulator, 16, 16, 16, float> acc[2][2];
        #pragma unroll
        for (int i = 0; i < 2; i++)
            #pragma unroll
            for (int j = 0; j < 2; j++) wmma::fill_fragment(acc[i][j], 0.f);
        #pragma unroll
        for (int kk = 0; kk < 128; kk += 16) {
            wmma::fragment<wmma::matrix_a, 16, 16, 16, __half, wmma::row_major> af[2];
            wmma::fragment<wmma::matrix_b, 16, 16, 16, __half, wmma::row_major> bf[2];
            #pragma unroll
            for (int i = 0; i < 2; i++)
                wmma::load_matrix_sync(af[i], sC + (wm * 32 + i * 16) * CLD + kk, CLD);
            #pragma unroll
            for (int j = 0; j < 2; j++)
                wmma::load_matrix_sync(bf[j], sH0 + kk * PLD + wn * 32 + j * 16, PLD);
            #pragma unroll
            for (int i = 0; i < 2; i++)
                #pragma unroll
                for (int j = 0; j < 2; j++)
                    wmma::mma_sync(acc[i][j], af[i], bf[j], acc[i][j]);
        }
        #pragma unroll
        for (int kk = 0; kk < 128; kk += 16) {
            wmma::fragment<wmma::matrix_a, 16, 16, 16, __half, wmma::row_major> af[2];
            wmma::fragment<wmma::matrix_b, 16, 16, 16, __half, wmma::row_major> bf[2];
            #pragma unroll
            for (int i = 0; i < 2; i++)
                wmma::load_matrix_sync(af[i], sB + (wm * 32 + i * 16) * CLD + kk, CLD);
            #pragma unroll
            for (int j = 0; j < 2; j++)
                wmma::load_matrix_sync(bf[j], sX + kk * PLD + wn * 32 + j * 16, PLD);
            #pragma unroll
            for (int i = 0; i < 2; i++)
                #pragma unroll
                for (int j = 0; j < 2; j++)
                    wmma::mma_sync(acc[i][j], af[i], bf[j], acc[i][j]);
        }
        __syncthreads();   // sS reads (mask) done block-wide; safe to overwrite as y
        #pragma unroll
        for (int i = 0; i < 2; i++)
            #pragma unroll
            for (int j = 0; j < 2; j++)
                wmma::store_matrix_sync(sS + (wm * 32 + i * 16) * PLD + wn * 32 + j * 16,
                                        acc[i][j], PLD, wmma::mem_row_major);
    }
    __syncthreads();

    // epilogue: y_t[p] += Dh * x_t[p] (fp32 x from global), write g_y
    {
        int r  = tid >> 1;
        int p0 = (tid & 1) * 32;
        const float* Xrow = base + (size_t)r * CONVCH + h * HEADDIM + p0;
        const float* Yrow = sS + r * PLD + p0;
        float* Orow = ybase + (size_t)r * DINNER + p0;
        #pragma unroll
        for (int j = 0; j < 8; j++) {
            float4 xv = *(const float4*)(Xrow + j * 4);
            float4 ov;
            ov.x = fmaf(Dh, xv.x, Yrow[j*4+0]);
            ov.y = fmaf(Dh, xv.y, Yrow[j*4+1]);
            ov.z = fmaf(Dh, xv.z, Yrow[j*4+2]);
            ov.w = fmaf(Dh, xv.w, Yrow[j*4+3]);
            *(float4*)(Orow + j * 4) = ov;
        }
    }
}

// ---------------- 4) gate (y * silu(z)) + RMSNorm (fp16 output) ---------------
__global__ void __launch_bounds__(256) gate_kernel(const float* __restrict__ norm_w) {
    __shared__ float red[32];
    int row = blockIdx.x;
    const float* zr = g_zx + (size_t)row * DPROJP;
    const float* yr = g_y + (size_t)row * DINNER;
    __half* yo = g_yh + (size_t)row * DINNER;
    float gbuf[6], ss = 0.f;
    #pragma unroll
    for (int i = 0; i < 6; i++) {
        int c = threadIdx.x + i * 256;
        float z = zr[c];
        float y = yr[c];
        float gv = y * (z / (1.f + expf(-z)));
        gbuf[i] = gv;
        ss += gv * gv;
    }
    float tot = block_reduce_sum(ss, red);
    float inv = rsqrtf(tot / DINNER + EPSV);
    #pragma unroll
    for (int i = 0; i < 6; i++) {
        int c = threadIdx.x + i * 256;
        yo[c] = __float2half_rn(gbuf[i] * inv * norm_w[c]);
    }
}

// ---------------- launcher ----------------------------------------------------
extern "C" void kernel_launch(void* const* d_in, const int* in_sizes, int n_in,
                              void* d_out, int out_size) {
    const float* x       = (const float*)d_in[0];
    const float* ln_w    = (const float*)d_in[1];
    const float* ln_b    = (const float*)d_in[2];
    const float* W_in    = (const float*)d_in[3];
    const float* conv_w  = (const float*)d_in[4];
    const float* conv_b  = (const float*)d_in[5];
    const float* A_log   = (const float*)d_in[6];
    const float* Dv      = (const float*)d_in[7];
    const float* dt_bias = (const float*)d_in[8];
    const float* norm_w  = (const float*)d_in[9];
    const float* W_out   = (const float*)d_in[10];
    float* out = (float*)d_out;

    __half *puh, *pyh, *pwinh, *pwouth;
    float  *pzx;
    cudaGetSymbolAddress((void**)&puh,    g_uh);
    cudaGetSymbolAddress((void**)&pzx,    g_zx);
    cudaGetSymbolAddress((void**)&pyh,    g_yh);
    cudaGetSymbolAddress((void**)&pwinh,  g_winh);
    cudaGetSymbolAddress((void**)&pwouth, g_wouth);

    cudaFuncSetAttribute(gemm_fp16<false>, cudaFuncAttributeMaxDynamicSharedMemorySize, GEMM_SMEM);
    cudaFuncSetAttribute(gemm_fp16<true>,  cudaFuncAttributeMaxDynamicSharedMemorySize, GEMM_SMEM);
    cudaFuncSetAttribute(scanAg_kernel,    cudaFuncAttributeMaxDynamicSharedMemorySize, SCANA_SMEM);
    cudaFuncSetAttribute(scanC_ssd,        cudaFuncAttributeMaxDynamicSharedMemorySize, SSD_SMEM);

    // idx 0: LN + weight conversion (grid tail)
    lnfused_kernel<<<NBT + CVTB, 256>>>(x, ln_w, ln_b, W_in, W_out);

    // idx 1: GEMM1 [16384x768]@[768x3456]
    dim3 g1(DPROJP / 128, NBT / 128);
    gemm_fp16<false><<<g1, 256, GEMM_SMEM>>>(puh, pwinh, pzx, nullptr,
                                             DPROJP, DPROJP, DMODEL);

    // idx 2: conv + SiLU, dt/dA in tail
    convdt_kernel<<<CONVBLK + DTBLK, 256>>>(conv_w, conv_b, dt_bias, A_log);

    // idx 3: scan pass A as tensor GEMM (profiled slot)
    scanAg_kernel<<<NBH * NCH, 256, SCANA_SMEM>>>();

    // idx 4: scan pass B (chunk-state chain)
    scanB_kernel<<<NBH * 8, 256>>>();

    // idx 5: scan pass C (SSD, tensor-core)
    scanC_ssd<<<NBH * NCH, 256, SSD_SMEM>>>(Dv, A_log);

    // idx 6: gate + RMSNorm
    gate_kernel<<<NBT, 256>>>(norm_w);

    // idx 7: GEMM2 [16384x1536]@[1536x768] + x
    dim3 g2(DMODEL / 128, NBT / 128);
    gemm_fp16<true><<<g2, 256, GEMM_SMEM>>>(pyh, pwouth, out, x,
                                            DMODEL, DMODEL, DINNER);
}